// round 2
// baseline (speedup 1.0000x reference)
#include <cuda_runtime.h>
#include <math.h>

// Problem constants (fixed by the reference setup_inputs).
#define BB     64
#define SS     2048
#define HH     1024
#define H4     (HH / 4)      // 256 float4 per row == NT, each thread owns one float4 slice
#define SPLITS 16
#define CHUNK  (SS / SPLITS) // 128 seq rows per CTA
#define NT     256
#define TS     8             // seq rows processed per iteration (MLP=8 float4 loads/thread)

// Scratch for split-K partials (static device globals: no allocation allowed).
__device__ float g_pm[BB * SPLITS];                       // per-split running max
__device__ float g_pl[BB * SPLITS];                       // per-split sum of exp
__device__ float g_pctx[(size_t)BB * SPLITS * HH];        // per-split partial context (4 MB)

// -----------------------------------------------------------------------------
// Pass 1: single streaming pass over enc_output with online softmax.
// grid = BB*SPLITS, block = NT. blockIdx.x = b*SPLITS + split.
// Writes raw scores into scores_out (the weights region of d_out, in-place).
// -----------------------------------------------------------------------------
__global__ __launch_bounds__(NT) void luong_pass1(
    const float* __restrict__ dec_h,
    const float* __restrict__ dec_c,
    const float* __restrict__ enc,
    float* __restrict__ scores_out)
{
    const int b     = blockIdx.x / SPLITS;
    const int split = blockIdx.x % SPLITS;
    const int t     = threadIdx.x;
    const int lane  = t & 31;
    const int wid   = t >> 5;

    // dec_state slice for this thread's 4 columns (read once, ~L2-resident).
    float4 dvec;
    {
        const float4* hp = (const float4*)(dec_h + (size_t)b * HH);
        const float4* cp = (const float4*)(dec_c + (size_t)b * HH);
        float4 a = hp[t], c = cp[t];
        dvec = make_float4(a.x + c.x, a.y + c.y, a.z + c.z, a.w + c.w);
    }

    const float4* erow = (const float4*)(enc + (size_t)b * SS * HH);
    const int s0 = split * CHUNK;

    float  m = -INFINITY;
    float  l = 0.0f;
    float4 acc = make_float4(0.f, 0.f, 0.f, 0.f);

    __shared__ float red[NT / 32][TS];

    for (int it = 0; it < CHUNK / TS; ++it) {
        const int s = s0 + it * TS;

        // 1) Load TS rows' worth of this thread's float4 (fully coalesced 4KB rows).
        float4 e[TS];
        #pragma unroll
        for (int j = 0; j < TS; ++j)
            e[j] = erow[(size_t)(s + j) * H4 + t];

        // 2) Partial dot with dec slice.
        float p[TS];
        #pragma unroll
        for (int j = 0; j < TS; ++j)
            p[j] = e[j].x * dvec.x + e[j].y * dvec.y + e[j].z * dvec.z + e[j].w * dvec.w;

        // 3) Warp reduce all TS partials, then cross-warp via smem.
        #pragma unroll
        for (int j = 0; j < TS; ++j) {
            #pragma unroll
            for (int o = 16; o > 0; o >>= 1)
                p[j] += __shfl_xor_sync(0xffffffffu, p[j], o);
        }
        if (lane == 0) {
            #pragma unroll
            for (int j = 0; j < TS; ++j) red[wid][j] = p[j];
        }
        __syncthreads();

        float score[TS];
        #pragma unroll
        for (int j = 0; j < TS; ++j) {
            float sum = 0.f;
            #pragma unroll
            for (int w = 0; w < NT / 32; ++w) sum += red[w][j];
            score[j] = sum;
        }
        __syncthreads();  // red reused next iteration

        // Stash raw scores (threads 0..TS-1 already hold the full sums).
        if (t < TS)
            scores_out[(size_t)b * SS + s + t] = score[t];

        // 4) Online softmax update, reusing e[j] still in registers (no re-read).
        float mt = score[0];
        #pragma unroll
        for (int j = 1; j < TS; ++j) mt = fmaxf(mt, score[j]);
        const float m_new = fmaxf(m, mt);
        const float scale = __expf(m - m_new);   // first iter: exp(-inf)=0, acc/l are 0
        acc.x *= scale; acc.y *= scale; acc.z *= scale; acc.w *= scale;
        l *= scale;
        #pragma unroll
        for (int j = 0; j < TS; ++j) {
            const float pe = __expf(score[j] - m_new);
            l += pe;
            acc.x += pe * e[j].x;
            acc.y += pe * e[j].y;
            acc.z += pe * e[j].z;
            acc.w += pe * e[j].w;
        }
        m = m_new;
    }

    // Emit per-split partials.
    ((float4*)g_pctx)[(size_t)blockIdx.x * H4 + t] = acc;
    if (t == 0) {
        g_pm[blockIdx.x] = m;
        g_pl[blockIdx.x] = l;
    }
}

// -----------------------------------------------------------------------------
// Pass 2: combine split partials per batch; write context and finalize weights
// in-place (raw scores -> exp(s - m) / l). grid = BB, block = NT.
// -----------------------------------------------------------------------------
__global__ __launch_bounds__(NT) void luong_pass2(
    float* __restrict__ ctx_out,
    float* __restrict__ weights_io)
{
    const int b = blockIdx.x;
    const int t = threadIdx.x;

    // Global max / sum across splits (computed redundantly per thread; tiny).
    float m = -INFINITY;
    #pragma unroll
    for (int i = 0; i < SPLITS; ++i)
        m = fmaxf(m, g_pm[b * SPLITS + i]);

    float w[SPLITS];
    float l = 0.f;
    #pragma unroll
    for (int i = 0; i < SPLITS; ++i) {
        w[i] = __expf(g_pm[b * SPLITS + i] - m);
        l += g_pl[b * SPLITS + i] * w[i];
    }
    const float invl = 1.0f / l;

    // Weighted combine of partial contexts.
    float4 acc = make_float4(0.f, 0.f, 0.f, 0.f);
    #pragma unroll
    for (int i = 0; i < SPLITS; ++i) {
        float4 c = ((const float4*)g_pctx)[(size_t)(b * SPLITS + i) * H4 + t];
        acc.x += w[i] * c.x;
        acc.y += w[i] * c.y;
        acc.z += w[i] * c.z;
        acc.w += w[i] * c.w;
    }
    acc.x *= invl; acc.y *= invl; acc.z *= invl; acc.w *= invl;
    ((float4*)(ctx_out))[(size_t)b * H4 + t] = acc;

    // Finalize attention weights in-place.
    for (int s = t; s < SS; s += NT) {
        const float sc = weights_io[(size_t)b * SS + s];
        weights_io[(size_t)b * SS + s] = __expf(sc - m) * invl;
    }
}

// -----------------------------------------------------------------------------
// Harness entry. Inputs (metadata order): dec_state_h [B,H] f32,
// dec_state_c [B,H] f32, enc_output [B,S,H] f32.
// Output: concat(context_vector [B,H], attention_weights [B,S,1]) f32.
// -----------------------------------------------------------------------------
extern "C" void kernel_launch(void* const* d_in, const int* in_sizes, int n_in,
                              void* d_out, int out_size)
{
    (void)in_sizes; (void)n_in; (void)out_size;
    const float* dec_h = (const float*)d_in[0];
    const float* dec_c = (const float*)d_in[1];
    const float* enc   = (const float*)d_in[2];
    float* out = (float*)d_out;
    float* ctx = out;                       // [B, H]
    float* wts = out + (size_t)BB * HH;     // [B, S, 1]

    luong_pass1<<<BB * SPLITS, NT>>>(dec_h, dec_c, enc, wts);
    luong_pass2<<<BB, NT>>>(ctx, wts);
}